// round 1
// baseline (speedup 1.0000x reference)
#include <cuda_runtime.h>
#include <cuda_bf16.h>
#include <mma.h>
#include <cstdint>

using namespace nvcuda;

#define B_  512
#define T_  256
#define V_  1000
#define E_  256
#define H_  512
#define G_  2048   // 4*H

// ---------------- static device scratch (no allocations allowed) ----------------
__device__ __align__(16) __nv_bfloat16 g_H[(T_ + 1)][B_][H_];   // h states; g_H[0] = 0, g_H[t+1] = output of step t (~134MB)
__device__ __align__(16) float          g_c[B_ * H_];           // cell state (1MB)
__device__ __align__(16) float          g_tab[V_][G_];          // emb@W_ih1^T + b_ih1 + b_hh1  (8MB)
__device__ __align__(16) __nv_bfloat16  g_Whh[G_][H_];          // bf16 W_hh1 (2MB)
__device__ __align__(16) __nv_bfloat16  g_Wout[1024][H_];       // bf16 W_out padded to 1024 rows (1MB)
__device__ __align__(16) float          g_logits[T_ * B_][1024];// raw logits scratch (~537MB)
__device__ int g_is64;                                          // ground_truth dtype sniff

// ---------------- init: dtype sniff, bf16 weight conversion, state zeroing ----------------
__global__ void init_kernel(const float* __restrict__ Whh1, const float* __restrict__ WoutF,
                            const void* __restrict__ gt_raw) {
    int stride = gridDim.x * blockDim.x;
    int tid0 = blockIdx.x * blockDim.x + threadIdx.x;
    if (tid0 == 0) {
        // If data is int64, the int32 view is [v0, 0, v1, 0, ...] (values < 1000).
        const int* p = (const int*)gt_raw;
        int z = (p[1] == 0) + (p[3] == 0) + (p[5] == 0) + (p[7] == 0) +
                (p[9] == 0) + (p[11] == 0) + (p[13] == 0) + (p[15] == 0);
        g_is64 = (z == 8) ? 1 : 0;
    }
    for (int i = tid0; i < G_ * H_; i += stride) {
        ((__nv_bfloat16*)g_Whh)[i] = __float2bfloat16(Whh1[i]);
        if (i < 1024 * H_) {
            float v = (i < V_ * H_) ? WoutF[i] : 0.f;
            ((__nv_bfloat16*)g_Wout)[i] = __float2bfloat16(v);
        }
        if (i < B_ * H_) {
            g_c[i] = 0.f;
            ((__nv_bfloat16*)g_H)[i] = __float2bfloat16(0.f);   // g_H[0] = h_init = 0
        }
    }
}

__device__ __forceinline__ int get_char(const void* gt, int b, int t) {
    // chars[b][t] = (t==0) ? EOS(0) : ground_truth[b][t-1]
    if (t == 0) return 0;
    int idx = b * T_ + (t - 1);
    if (g_is64) return (int)((const long long*)gt)[idx];
    return ((const int*)gt)[idx];
}

// ---------------- ih gate table: g_tab[v][g] = emb[v] . W_ih1[g] + b_ih1[g] + b_hh1[g] ----------------
__global__ void table_kernel(const float* __restrict__ emb, const float* __restrict__ Wih,
                             const float* __restrict__ bih, const float* __restrict__ bhh) {
    int gtile = blockIdx.x;  // 0..31 -> 64 g cols
    int vtile = blockIdx.y;  // 0..15 -> 64 v rows (padded past 1000)
    __shared__ float sE[64][65];
    __shared__ float sW[64][65];
    float acc[4][4] = {};
    int tm = threadIdx.x >> 4, tn = threadIdx.x & 15;
    for (int kc = 0; kc < 4; kc++) {
        for (int i = threadIdx.x; i < 64 * 64; i += 256) {
            int r = i >> 6, c = i & 63;
            int v = vtile * 64 + r;
            sE[r][c] = (v < V_) ? emb[v * E_ + kc * 64 + c] : 0.f;
            sW[r][c] = Wih[(gtile * 64 + r) * E_ + kc * 64 + c];
        }
        __syncthreads();
        #pragma unroll 8
        for (int k = 0; k < 64; k++) {
            float e[4], w[4];
            #pragma unroll
            for (int mi = 0; mi < 4; mi++) e[mi] = sE[tm * 4 + mi][k];
            #pragma unroll
            for (int ni = 0; ni < 4; ni++) w[ni] = sW[tn * 4 + ni][k];
            #pragma unroll
            for (int mi = 0; mi < 4; mi++)
                #pragma unroll
                for (int ni = 0; ni < 4; ni++) acc[mi][ni] += e[mi] * w[ni];
        }
        __syncthreads();
    }
    #pragma unroll
    for (int mi = 0; mi < 4; mi++) {
        int v = vtile * 64 + tm * 4 + mi;
        if (v >= V_) continue;
        #pragma unroll
        for (int ni = 0; ni < 4; ni++) {
            int g = gtile * 64 + tn * 4 + ni;
            g_tab[v][g] = acc[mi][ni] + bih[g] + bhh[g];
        }
    }
}

// ---------------- one recurrence step: gates = h_in @ Whh^T (+table), LSTM pointwise ----------------
// grid (32 htiles x 16 btiles), 128 threads = 4 warps (one per gate i/f/g/o)
__global__ void step_kernel(int t, const void* __restrict__ gt) {
    const int ht = blockIdx.x;   // 16 hidden cols
    const int bt = blockIdx.y;   // 32 batch rows
    __shared__ __nv_bfloat16 sA[32 * 512];   // 32KB h_in tile
    __shared__ float sg[4][32][16];          // 8KB gate tile

    // stage A tile (contiguous 32KB)
    {
        const uint4* src = (const uint4*)&g_H[t][bt * 32][0];
        uint4* dst = (uint4*)sA;
        #pragma unroll
        for (int i = threadIdx.x; i < 2048; i += 128) dst[i] = src[i];
    }
    __syncthreads();

    int q = threadIdx.x >> 5;  // gate index
    wmma::fragment<wmma::accumulator, 16, 16, 16, float> acc[2];
    wmma::fill_fragment(acc[0], 0.f);
    wmma::fill_fragment(acc[1], 0.f);
    const __nv_bfloat16* Bbase = &g_Whh[q * H_ + ht * 16][0];  // col-major (k,n) @ n*512+k
    #pragma unroll 4
    for (int kk = 0; kk < 32; kk++) {
        wmma::fragment<wmma::matrix_b, 16, 16, 16, __nv_bfloat16, wmma::col_major> fb;
        wmma::load_matrix_sync(fb, Bbase + kk * 16, 512);
        #pragma unroll
        for (int mi = 0; mi < 2; mi++) {
            wmma::fragment<wmma::matrix_a, 16, 16, 16, __nv_bfloat16, wmma::row_major> fa;
            wmma::load_matrix_sync(fa, sA + (mi * 16) * 512 + kk * 16, 512);
            wmma::mma_sync(acc[mi], fa, fb, acc[mi]);
        }
    }
    wmma::store_matrix_sync(&sg[q][0][0],  acc[0], 16, wmma::mem_row_major);
    wmma::store_matrix_sync(&sg[q][16][0], acc[1], 16, wmma::mem_row_major);
    __syncthreads();

    // fused LSTM pointwise
    for (int idx = threadIdx.x; idx < 32 * 16; idx += 128) {
        int bl = idx >> 4, hl = idx & 15;
        int b = bt * 32 + bl;
        int h = ht * 16 + hl;
        int ch = get_char(gt, b, t);
        const float* tab = g_tab[ch];
        float gi = sg[0][bl][hl] + tab[h];
        float gf = sg[1][bl][hl] + tab[H_ + h];
        float gg = sg[2][bl][hl] + tab[2 * H_ + h];
        float go = sg[3][bl][hl] + tab[3 * H_ + h];
        gi = 1.f / (1.f + __expf(-gi));
        gf = 1.f / (1.f + __expf(-gf));
        gg = tanhf(gg);
        go = 1.f / (1.f + __expf(-go));
        float c = gf * g_c[b * H_ + h] + gi * gg;
        g_c[b * H_ + h] = c;
        float hv = go * tanhf(c);
        g_H[t + 1][b][h] = __float2bfloat16(hv);
    }
}

// ---------------- batched output projection: logits = H_all @ Wout^T -> g_logits ----------------
// grid (4 ntiles x 2048 mtiles), 256 threads = 8 warps (2m x 4n), block tile 64m x 256n, K chunks of 64
__global__ void logits_kernel() {
    int nt = blockIdx.x, mt = blockIdx.y;
    __shared__ __nv_bfloat16 sA[64 * 64];    // 8KB
    __shared__ __nv_bfloat16 sB[256 * 64];   // 32KB
    const __nv_bfloat16* A = &g_H[1][0][0];  // [131072][512], row r = t*512+b

    int warp = threadIdx.x >> 5;
    int wm = warp >> 2;   // 0..1
    int wn = warp & 3;    // 0..3
    wmma::fragment<wmma::accumulator, 16, 16, 16, float> acc[2][4];
    #pragma unroll
    for (int mi = 0; mi < 2; mi++)
        #pragma unroll
        for (int ni = 0; ni < 4; ni++) wmma::fill_fragment(acc[mi][ni], 0.f);

    for (int kc = 0; kc < 8; kc++) {
        #pragma unroll
        for (int i = threadIdx.x; i < 512; i += 256) {   // A chunk 64x64
            int r = i >> 3, c8 = i & 7;
            ((uint4*)sA)[i] = *(const uint4*)&A[(mt * 64 + r) * 512 + kc * 64 + c8 * 8];
        }
        #pragma unroll
        for (int i = threadIdx.x; i < 2048; i += 256) {  // B chunk 256x64
            int n = i >> 3, c8 = i & 7;
            ((uint4*)sB)[i] = *(const uint4*)&g_Wout[nt * 256 + n][kc * 64 + c8 * 8];
        }
        __syncthreads();
        #pragma unroll
        for (int kk = 0; kk < 4; kk++) {
            wmma::fragment<wmma::matrix_a, 16, 16, 16, __nv_bfloat16, wmma::row_major> fa[2];
            #pragma unroll
            for (int mi = 0; mi < 2; mi++)
                wmma::load_matrix_sync(fa[mi], &sA[(wm * 32 + mi * 16) * 64 + kk * 16], 64);
            #pragma unroll
            for (int ni = 0; ni < 4; ni++) {
                wmma::fragment<wmma::matrix_b, 16, 16, 16, __nv_bfloat16, wmma::col_major> fb;
                wmma::load_matrix_sync(fb, &sB[(wn * 64 + ni * 16) * 64 + kk * 16], 64);
                #pragma unroll
                for (int mi = 0; mi < 2; mi++)
                    wmma::mma_sync(acc[mi][ni], fa[mi], fb, acc[mi][ni]);
            }
        }
        __syncthreads();
    }
    #pragma unroll
    for (int mi = 0; mi < 2; mi++)
        #pragma unroll
        for (int ni = 0; ni < 4; ni++) {
            int row = mt * 64 + wm * 32 + mi * 16;
            int col = nt * 256 + wn * 64 + ni * 16;
            wmma::store_matrix_sync(&g_logits[row][col], acc[mi][ni], 1024, wmma::mem_row_major);
        }
}

// ---------------- log_softmax + bias + layout remap -> d_out ----------------
// one block (256 thr) per row; row = t*512+b -> out row b*256+t
__global__ void softmax_kernel(float* __restrict__ out, const float* __restrict__ bout) {
    int row = blockIdx.x;
    int t = row >> 9, b = row & 511;
    const float* lg = g_logits[row];
    __shared__ float red[256];

    float v[4];
    float mx = -1e30f;
    #pragma unroll
    for (int j = 0; j < 4; j++) {
        int c = threadIdx.x + j * 256;
        v[j] = (c < V_) ? (lg[c] + bout[c]) : -1e30f;
        mx = fmaxf(mx, v[j]);
    }
    red[threadIdx.x] = mx;
    __syncthreads();
    for (int s = 128; s > 0; s >>= 1) {
        if (threadIdx.x < s) red[threadIdx.x] = fmaxf(red[threadIdx.x], red[threadIdx.x + s]);
        __syncthreads();
    }
    mx = red[0];
    __syncthreads();

    float sum = 0.f;
    #pragma unroll
    for (int j = 0; j < 4; j++) {
        int c = threadIdx.x + j * 256;
        if (c < V_) sum += __expf(v[j] - mx);
    }
    red[threadIdx.x] = sum;
    __syncthreads();
    for (int s = 128; s > 0; s >>= 1) {
        if (threadIdx.x < s) red[threadIdx.x] += red[threadIdx.x + s];
        __syncthreads();
    }
    float lse = mx + logf(red[0]);

    float* o = out + ((size_t)b * T_ + t) * V_;
    #pragma unroll
    for (int j = 0; j < 4; j++) {
        int c = threadIdx.x + j * 256;
        if (c < V_) o[c] = v[j] - lse;
    }
}

// ---------------- launch ----------------
extern "C" void kernel_launch(void* const* d_in, const int* in_sizes, int n_in,
                              void* d_out, int out_size) {
    // metadata order:
    // 0 listener_output (unused), 1 ground_truth, 2 emb,
    // 3..6 W_ih0/W_hh0/b_ih0/b_hh0 (dead cell 0 — unused),
    // 7 W_ih1, 8 W_hh1, 9 b_ih1, 10 b_hh1, 11 W_out, 12 b_out
    const void*  gt   = d_in[1];
    const float* emb  = (const float*)d_in[2];
    const float* Wih1 = (const float*)d_in[7];
    const float* Whh1 = (const float*)d_in[8];
    const float* bih1 = (const float*)d_in[9];
    const float* bhh1 = (const float*)d_in[10];
    const float* Wout = (const float*)d_in[11];
    const float* bout = (const float*)d_in[12];
    float* out = (float*)d_out;

    init_kernel<<<1024, 256>>>(Whh1, Wout, gt);
    table_kernel<<<dim3(32, 16), 256>>>(emb, Wih1, bih1, bhh1);
    for (int t = 0; t < T_; t++)
        step_kernel<<<dim3(32, 16), 128>>>(t, gt);
    logits_kernel<<<dim3(4, 2048), 256>>>();
    softmax_kernel<<<T_ * B_, 256>>>(out, bout);
}

// round 2
// speedup vs baseline: 2.6431x; 2.6431x over previous
#include <cuda_runtime.h>
#include <cuda_bf16.h>
#include <mma.h>
#include <cstdint>

using namespace nvcuda;

#define B_  512
#define T_  256
#define V_  1000
#define E_  256
#define H_  512
#define G_  2048   // 4*H

#define LDW 520    // padded leading dim (elems) for bf16 smem tiles: 1040B stride, conflict-free
#define LDG_ 132   // padded leading dim (floats) for gate buffer

// ---------------- static device scratch (no allocations allowed) ----------------
__device__ __align__(16) __nv_bfloat16 g_H[(T_ + 1)][B_][H_];   // h states; g_H[0]=0 (~134MB)
__device__ __align__(16) float          g_tab[V_][G_];          // emb@W_ih1^T + b_ih1 + b_hh1 (8MB)
__device__ __align__(16) __nv_bfloat16  g_Whh[G_][H_];          // bf16 W_hh1 (2MB)
__device__ __align__(16) __nv_bfloat16  g_Wout[1024][H_];       // bf16 W_out padded (1MB)
__device__ __align__(16) float          g_logits[T_ * B_][1024];// logits scratch (~537MB)
__device__ __align__(16) short          g_chars[T_][B_];        // input char per (t,b)
__device__ int g_bar_count;
__device__ volatile int g_bar_release;

// ---------------- init: weights->bf16, chars table, state/barrier reset ----------------
__global__ void init_kernel(const float* __restrict__ Whh1, const float* __restrict__ WoutF,
                            const void* __restrict__ gt_raw) {
    int stride = gridDim.x * blockDim.x;
    int tid0 = blockIdx.x * blockDim.x + threadIdx.x;
    if (tid0 == 0) { g_bar_count = 0; g_bar_release = 0; }
    // dtype sniff (every thread, no race): int64 view shows zero upper words
    const int* p = (const int*)gt_raw;
    int z = (p[1] == 0) + (p[3] == 0) + (p[5] == 0) + (p[7] == 0) +
            (p[9] == 0) + (p[11] == 0) + (p[13] == 0) + (p[15] == 0);
    int is64 = (z == 8);
    for (int i = tid0; i < G_ * H_; i += stride) {
        ((__nv_bfloat16*)g_Whh)[i] = __float2bfloat16(Whh1[i]);
        if (i < 1024 * H_) {
            float v = (i < V_ * H_) ? WoutF[i] : 0.f;
            ((__nv_bfloat16*)g_Wout)[i] = __float2bfloat16(v);
        }
        if (i < B_ * H_) ((__nv_bfloat16*)g_H)[i] = __float2bfloat16(0.f);  // g_H[0] = 0
        if (i < T_ * B_) {
            int t = i / B_, b = i % B_;
            int ch = 0;
            if (t > 0) {
                int idx = b * T_ + (t - 1);
                ch = is64 ? (int)((const long long*)gt_raw)[idx] : ((const int*)gt_raw)[idx];
            }
            ((short*)g_chars)[i] = (short)ch;
        }
    }
}

// ---------------- ih gate table: g_tab[v][g] = emb[v] . W_ih1[g] + b_ih1[g] + b_hh1[g] ----------------
__global__ void table_kernel(const float* __restrict__ emb, const float* __restrict__ Wih,
                             const float* __restrict__ bih, const float* __restrict__ bhh) {
    int gtile = blockIdx.x;  // 0..31 -> 64 g cols
    int vtile = blockIdx.y;  // 0..15 -> 64 v rows
    __shared__ float sE[64][65];
    __shared__ float sW[64][65];
    float acc[4][4] = {};
    int tm = threadIdx.x >> 4, tn = threadIdx.x & 15;
    for (int kc = 0; kc < 4; kc++) {
        for (int i = threadIdx.x; i < 64 * 64; i += 256) {
            int r = i >> 6, c = i & 63;
            int v = vtile * 64 + r;
            sE[r][c] = (v < V_) ? emb[v * E_ + kc * 64 + c] : 0.f;
            sW[r][c] = Wih[(gtile * 64 + r) * E_ + kc * 64 + c];
        }
        __syncthreads();
        #pragma unroll 8
        for (int k = 0; k < 64; k++) {
            float e[4], w[4];
            #pragma unroll
            for (int mi = 0; mi < 4; mi++) e[mi] = sE[tm * 4 + mi][k];
            #pragma unroll
            for (int ni = 0; ni < 4; ni++) w[ni] = sW[tn * 4 + ni][k];
            #pragma unroll
            for (int mi = 0; mi < 4; mi++)
                #pragma unroll
                for (int ni = 0; ni < 4; ni++) acc[mi][ni] += e[mi] * w[ni];
        }
        __syncthreads();
    }
    #pragma unroll
    for (int mi = 0; mi < 4; mi++) {
        int v = vtile * 64 + tm * 4 + mi;
        if (v >= V_) continue;
        #pragma unroll
        for (int ni = 0; ni < 4; ni++) {
            int g = gtile * 64 + tn * 4 + ni;
            g_tab[v][g] = acc[mi][ni] + bih[g] + bhh[g];
        }
    }
}

// ---------------- persistent recurrence kernel ----------------
// grid = 128 blocks: block = (bt, gt) with bt = bid>>4 (8 tiles of 64 batch),
// gt = bid&15 (16 tiles of 32 h-cols, each with all 4 gates).
// SMEM: W slice (128 rows x 512, resident all 256 steps), A tile (64x512 per step),
//       c-state tile (64x32 fp32, resident), gate buffer reuses A region.
#define SMEM_BYTES ((128 * LDW + 64 * LDW) * 2 + 64 * 32 * 4)

__global__ __launch_bounds__(256, 1) void recur_kernel() {
    extern __shared__ __nv_bfloat16 smem[];
    __nv_bfloat16* sW = smem;                       // 128 x LDW
    __nv_bfloat16* sA = smem + 128 * LDW;           // 64 x LDW
    float* sC = (float*)(smem + (128 + 64) * LDW);  // 64 x 32
    float* sG = (float*)sA;                         // 64 x LDG_ (reuse after GEMM)

    const int gt = blockIdx.x & 15;
    const int bt = blockIdx.x >> 4;
    const int b0 = bt * 64;

    // load W slice once: row r in [0,128): gate q=r>>5, h-col gt*32+(r&31)
    for (int i = threadIdx.x; i < 128 * 64; i += 256) {
        int r = i >> 6, c = i & 63;
        int grow = (r >> 5) * H_ + gt * 32 + (r & 31);
        ((uint4*)(sW + r * LDW))[c] = *(const uint4*)&g_Whh[grow][c * 8];
    }
    for (int i = threadIdx.x; i < 64 * 32; i += 256) sC[i] = 0.f;
    __syncthreads();

    const int warp = threadIdx.x >> 5;
    const int wm = warp >> 2;   // 0..1 (32 batch rows each)
    const int wn = warp & 3;    // 0..3 (32 gate cols each)

    for (int t = 0; t < T_; t++) {
        // stage A = h_t tile [64 x 512]
        for (int i = threadIdx.x; i < 64 * 64; i += 256) {
            int r = i >> 6, c = i & 63;
            ((uint4*)(sA + r * LDW))[c] = *(const uint4*)&g_H[t][b0 + r][c * 8];
        }
        __syncthreads();

        wmma::fragment<wmma::accumulator, 16, 16, 16, float> acc[2][2];
        #pragma unroll
        for (int mi = 0; mi < 2; mi++)
            #pragma unroll
            for (int ni = 0; ni < 2; ni++) wmma::fill_fragment(acc[mi][ni], 0.f);

        #pragma unroll 4
        for (int kk = 0; kk < 32; kk++) {
            wmma::fragment<wmma::matrix_b, 16, 16, 16, __nv_bfloat16, wmma::col_major> fb[2];
            #pragma unroll
            for (int ni = 0; ni < 2; ni++)
                wmma::load_matrix_sync(fb[ni], sW + (wn * 32 + ni * 16) * LDW + kk * 16, LDW);
            #pragma unroll
            for (int mi = 0; mi < 2; mi++) {
                wmma::fragment<wmma::matrix_a, 16, 16, 16, __nv_bfloat16, wmma::row_major> fa;
                wmma::load_matrix_sync(fa, sA + (wm * 32 + mi * 16) * LDW + kk * 16, LDW);
                #pragma unroll
                for (int ni = 0; ni < 2; ni++)
                    wmma::mma_sync(acc[mi][ni], fa, fb[ni], acc[mi][ni]);
            }
        }
        __syncthreads();   // all warps done reading sA -> safe to overwrite with gates

        #pragma unroll
        for (int mi = 0; mi < 2; mi++)
            #pragma unroll
            for (int ni = 0; ni < 2; ni++)
                wmma::store_matrix_sync(sG + (wm * 32 + mi * 16) * LDG_ + (wn * 32 + ni * 16),
                                        acc[mi][ni], LDG_, wmma::mem_row_major);
        __syncthreads();

        // fused LSTM pointwise: 64 batch x 32 h
        for (int i = threadIdx.x; i < 64 * 32; i += 256) {
            int bl = i >> 5, hl = i & 31;
            int b = b0 + bl;
            int ch = g_chars[t][b];
            const float* tab = g_tab[ch];
            int hcol = gt * 32 + hl;
            float gi = sG[bl * LDG_ + hl]      + tab[hcol];
            float gf = sG[bl * LDG_ + 32 + hl] + tab[H_ + hcol];
            float gg = sG[bl * LDG_ + 64 + hl] + tab[2 * H_ + hcol];
            float go = sG[bl * LDG_ + 96 + hl] + tab[3 * H_ + hcol];
            gi = 1.f / (1.f + __expf(-gi));
            gf = 1.f / (1.f + __expf(-gf));
            gg = tanhf(gg);
            go = 1.f / (1.f + __expf(-go));
            float c = gf * sC[i] + gi * gg;
            sC[i] = c;
            g_H[t + 1][b][hcol] = __float2bfloat16(go * tanhf(c));
        }

        // grid barrier (all 128 blocks co-resident)
        __threadfence();
        __syncthreads();
        if (threadIdx.x == 0) {
            int v = atomicAdd(&g_bar_count, 1);
            if (v == gridDim.x - 1) {
                g_bar_count = 0;
                __threadfence();
                atomicExch((int*)&g_bar_release, t + 1);
            } else {
                while (g_bar_release < t + 1) __nanosleep(32);
                __threadfence();
            }
        }
        __syncthreads();
    }
}

// ---------------- batched output projection: logits = H_all @ Wout^T -> g_logits ----------------
// grid (4 ntiles x 2048 mtiles), 256 threads = 8 warps (2m x 4n), tile 64m x 256n, K chunks 64
__global__ void logits_kernel() {
    int nt = blockIdx.x, mt = blockIdx.y;
    __shared__ __nv_bfloat16 sA[64 * 72];    // padded ld=72 (conflict-free)
    __shared__ __nv_bfloat16 sB[256 * 72];
    const __nv_bfloat16* A = &g_H[1][0][0];  // [131072][512], row r = t*512+b

    int warp = threadIdx.x >> 5;
    int wm = warp >> 2;   // 0..1
    int wn = warp & 3;    // 0..3
    wmma::fragment<wmma::accumulator, 16, 16, 16, float> acc[2][4];
    #pragma unroll
    for (int mi = 0; mi < 2; mi++)
        #pragma unroll
        for (int ni = 0; ni < 4; ni++) wmma::fill_fragment(acc[mi][ni], 0.f);

    for (int kc = 0; kc < 8; kc++) {
        #pragma unroll
        for (int i = threadIdx.x; i < 512; i += 256) {   // A chunk 64x64
            int r = i >> 3, c8 = i & 7;
            *(uint4*)(sA + r * 72 + c8 * 8) = *(const uint4*)&A[(mt * 64 + r) * 512 + kc * 64 + c8 * 8];
        }
        #pragma unroll
        for (int i = threadIdx.x; i < 2048; i += 256) {  // B chunk 256x64
            int n = i >> 3, c8 = i & 7;
            *(uint4*)(sB + n * 72 + c8 * 8) = *(const uint4*)&g_Wout[nt * 256 + n][kc * 64 + c8 * 8];
        }
        __syncthreads();
        #pragma unroll
        for (int kk = 0; kk < 4; kk++) {
            wmma::fragment<wmma::matrix_a, 16, 16, 16, __nv_bfloat16, wmma::row_major> fa[2];
            #pragma unroll
            for (int mi = 0; mi < 2; mi++)
                wmma::load_matrix_sync(fa[mi], sA + (wm * 32 + mi * 16) * 72 + kk * 16, 72);
            #pragma unroll
            for (int ni = 0; ni < 4; ni++) {
                wmma::fragment<wmma::matrix_b, 16, 16, 16, __nv_bfloat16, wmma::col_major> fb;
                wmma::load_matrix_sync(fb, sB + (wn * 64 + ni * 16) * 72 + kk * 16, 72);
                #pragma unroll
                for (int mi = 0; mi < 2; mi++)
                    wmma::mma_sync(acc[mi][ni], fa[mi], fb, acc[mi][ni]);
            }
        }
        __syncthreads();
    }
    #pragma unroll
    for (int mi = 0; mi < 2; mi++)
        #pragma unroll
        for (int ni = 0; ni < 4; ni++) {
            int row = mt * 64 + wm * 32 + mi * 16;
            int col = nt * 256 + wn * 64 + ni * 16;
            wmma::store_matrix_sync(&g_logits[row][col], acc[mi][ni], 1024, wmma::mem_row_major);
        }
}

// ---------------- log_softmax + bias + layout remap -> d_out ----------------
__global__ void softmax_kernel(float* __restrict__ out, const float* __restrict__ bout) {
    int row = blockIdx.x;
    int t = row >> 9, b = row & 511;
    const float* lg = g_logits[row];
    __shared__ float red[256];

    float v[4];
    float mx = -1e30f;
    #pragma unroll
    for (int j = 0; j < 4; j++) {
        int c = threadIdx.x + j * 256;
        v[j] = (c < V_) ? (lg[c] + bout[c]) : -1e30f;
        mx = fmaxf(mx, v[j]);
    }
    red[threadIdx.x] = mx;
    __syncthreads();
    for (int s = 128; s > 0; s >>= 1) {
        if (threadIdx.x < s) red[threadIdx.x] = fmaxf(red[threadIdx.x], red[threadIdx.x + s]);
        __syncthreads();
    }
    mx = red[0];
    __syncthreads();

    float sum = 0.f;
    #pragma unroll
    for (int j = 0; j < 4; j++) {
        int c = threadIdx.x + j * 256;
        if (c < V_) sum += __expf(v[j] - mx);
    }
    red[threadIdx.x] = sum;
    __syncthreads();
    for (int s = 128; s > 0; s >>= 1) {
        if (threadIdx.x < s) red[threadIdx.x] += red[threadIdx.x + s];
        __syncthreads();
    }
    float lse = mx + logf(red[0]);

    float* o = out + ((size_t)b * T_ + t) * V_;
    #pragma unroll
    for (int j = 0; j < 4; j++) {
        int c = threadIdx.x + j * 256;
        if (c < V_) o[c] = v[j] - lse;
    }
}

// ---------------- launch ----------------
extern "C" void kernel_launch(void* const* d_in, const int* in_sizes, int n_in,
                              void* d_out, int out_size) {
    const void*  gt   = d_in[1];
    const float* emb  = (const float*)d_in[2];
    const float* Wih1 = (const float*)d_in[7];
    const float* Whh1 = (const float*)d_in[8];
    const float* bih1 = (const float*)d_in[9];
    const float* bhh1 = (const float*)d_in[10];
    const float* Wout = (const float*)d_in[11];
    const float* bout = (const float*)d_in[12];
    float* out = (float*)d_out;

    cudaFuncSetAttribute(recur_kernel, cudaFuncAttributeMaxDynamicSharedMemorySize, SMEM_BYTES);

    init_kernel<<<1024, 256>>>(Whh1, Wout, gt);
    table_kernel<<<dim3(32, 16), 256>>>(emb, Wih1, bih1, bhh1);
    recur_kernel<<<128, 256, SMEM_BYTES>>>();
    logits_kernel<<<dim3(4, 2048), 256>>>();
    softmax_kernel<<<T_ * B_, 256>>>(out, bout);
}

// round 4
// speedup vs baseline: 3.1296x; 1.1840x over previous
#include <cuda_runtime.h>
#include <cuda_bf16.h>
#include <mma.h>
#include <cstdint>

using namespace nvcuda;

#define B_  512
#define T_  256
#define V_  1000
#define E_  256
#define H_  512
#define G_  2048   // 4*H

#define LDW 520    // padded leading dim (elems) for bf16 smem tiles: 1040B stride, conflict-free
#define LDG_ 132   // padded leading dim (floats) for gate buffer

// ---------------- fast activations (single-MUFU) ----------------
__device__ __forceinline__ float tanh_fast(float x) {
    float y; asm("tanh.approx.f32 %0, %1;" : "=f"(y) : "f"(x)); return y;
}
__device__ __forceinline__ float sigmoid_fast(float x) {
    return fmaf(0.5f, tanh_fast(0.5f * x), 0.5f);
}

// ---------------- static device scratch ----------------
__device__ __align__(16) __nv_bfloat16 g_H[(T_ + 1)][B_][H_];   // h states (~134MB)
__device__ __align__(16) float          g_tab[V_][G_];          // emb@W_ih1^T + b_ih1 + b_hh1 (8MB)
__device__ __align__(16) __nv_bfloat16  g_Whh[G_][H_];          // bf16 W_hh1 (2MB)
__device__ __align__(16) __nv_bfloat16  g_Wout[1024][H_];       // bf16 W_out padded (1MB)
__device__ __align__(16) float          g_logits[T_ * B_][1024];// logits scratch (~537MB)
__device__ __align__(16) short          g_chars[T_][B_];
__device__ int g_cnt[8 * 32];            // per-bt barrier counters, 128B apart
__device__ volatile int g_rel[8 * 32];

// ---------------- init ----------------
__global__ void init_kernel(const float* __restrict__ Whh1, const float* __restrict__ WoutF,
                            const void* __restrict__ gt_raw) {
    int stride = gridDim.x * blockDim.x;
    int tid0 = blockIdx.x * blockDim.x + threadIdx.x;
    if (tid0 < 8) { g_cnt[tid0 * 32] = 0; g_rel[tid0 * 32] = 0; }
    const int* p = (const int*)gt_raw;
    int z = (p[1] == 0) + (p[3] == 0) + (p[5] == 0) + (p[7] == 0) +
            (p[9] == 0) + (p[11] == 0) + (p[13] == 0) + (p[15] == 0);
    int is64 = (z == 8);
    for (int i = tid0; i < G_ * H_; i += stride) {
        ((__nv_bfloat16*)g_Whh)[i] = __float2bfloat16(Whh1[i]);
        if (i < 1024 * H_) {
            float v = (i < V_ * H_) ? WoutF[i] : 0.f;
            ((__nv_bfloat16*)g_Wout)[i] = __float2bfloat16(v);
        }
        if (i < B_ * H_) ((__nv_bfloat16*)g_H)[i] = __float2bfloat16(0.f);
        if (i < T_ * B_) {
            int t = i / B_, b = i % B_;
            int ch = 0;
            if (t > 0) {
                int idx = b * T_ + (t - 1);
                ch = is64 ? (int)((const long long*)gt_raw)[idx] : ((const int*)gt_raw)[idx];
            }
            ((short*)g_chars)[i] = (short)ch;
        }
    }
}

// ---------------- ih gate table ----------------
__global__ void table_kernel(const float* __restrict__ emb, const float* __restrict__ Wih,
                             const float* __restrict__ bih, const float* __restrict__ bhh) {
    int gtile = blockIdx.x;
    int vtile = blockIdx.y;
    __shared__ float sE[64][65];
    __shared__ float sW[64][65];
    float acc[4][4] = {};
    int tm = threadIdx.x >> 4, tn = threadIdx.x & 15;
    for (int kc = 0; kc < 4; kc++) {
        for (int i = threadIdx.x; i < 64 * 64; i += 256) {
            int r = i >> 6, c = i & 63;
            int v = vtile * 64 + r;
            sE[r][c] = (v < V_) ? emb[v * E_ + kc * 64 + c] : 0.f;
            sW[r][c] = Wih[(gtile * 64 + r) * E_ + kc * 64 + c];
        }
        __syncthreads();
        #pragma unroll 8
        for (int k = 0; k < 64; k++) {
            float e[4], w[4];
            #pragma unroll
            for (int mi = 0; mi < 4; mi++) e[mi] = sE[tm * 4 + mi][k];
            #pragma unroll
            for (int ni = 0; ni < 4; ni++) w[ni] = sW[tn * 4 + ni][k];
            #pragma unroll
            for (int mi = 0; mi < 4; mi++)
                #pragma unroll
                for (int ni = 0; ni < 4; ni++) acc[mi][ni] += e[mi] * w[ni];
        }
        __syncthreads();
    }
    #pragma unroll
    for (int mi = 0; mi < 4; mi++) {
        int v = vtile * 64 + tm * 4 + mi;
        if (v >= V_) continue;
        #pragma unroll
        for (int ni = 0; ni < 4; ni++) {
            int g = gtile * 64 + tn * 4 + ni;
            g_tab[v][g] = acc[mi][ni] + bih[g] + bhh[g];
        }
    }
}

// ---------------- persistent recurrence kernel ----------------
// 128 blocks: bt = bid>>4 (8 x 64 batch rows), gt = bid&15 (16 x 32 h-cols -> 128 gate cols).
// SMEM: W slice (128 x LDW, resident), A tile (64 x LDW per step), gate buffer reuses A.
// c-state in registers (8/thread). Per-bt 16-block barrier.
#define SMEM_BYTES ((128 * LDW + 64 * LDW) * 2)

__global__ __launch_bounds__(256, 1) void recur_kernel() {
    extern __shared__ __nv_bfloat16 smem[];
    __nv_bfloat16* sW = smem;                       // 128 x LDW
    __nv_bfloat16* sA = smem + 128 * LDW;           // 64 x LDW
    float* sG = (float*)sA;                         // 64 x LDG_ (reuse after GEMM)

    const int gt = blockIdx.x & 15;
    const int bt = blockIdx.x >> 4;
    const int b0 = bt * 64;

    // load W slice once: row r in [0,128): gate q=r>>5, h-col gt*32+(r&31)
    for (int i = threadIdx.x; i < 128 * 64; i += 256) {
        int r = i >> 6, c = i & 63;
        int grow = (r >> 5) * H_ + gt * 32 + (r & 31);
        ((uint4*)(sW + r * LDW))[c] = *(const uint4*)&g_Whh[grow][c * 8];
    }
    __syncthreads();

    const int warp = threadIdx.x >> 5;
    const int wm = warp >> 2;   // 0..1 (32 batch rows each)
    const int wn = warp & 3;    // 0..3 (32 gate cols each)

    float creg[8];
    #pragma unroll
    for (int j = 0; j < 8; j++) creg[j] = 0.f;

    for (int t = 0; t < T_; t++) {
        // stage A = h_t tile [64 x 512]
        for (int i = threadIdx.x; i < 64 * 64; i += 256) {
            int r = i >> 6, c = i & 63;
            ((uint4*)(sA + r * LDW))[c] = *(const uint4*)&g_H[t][b0 + r][c * 8];
        }
        __syncthreads();

        wmma::fragment<wmma::accumulator, 16, 16, 16, float> acc[2][2];
        #pragma unroll
        for (int mi = 0; mi < 2; mi++)
            #pragma unroll
            for (int ni = 0; ni < 2; ni++) wmma::fill_fragment(acc[mi][ni], 0.f);

        #pragma unroll 4
        for (int kk = 0; kk < 32; kk++) {
            wmma::fragment<wmma::matrix_b, 16, 16, 16, __nv_bfloat16, wmma::col_major> fb[2];
            #pragma unroll
            for (int ni = 0; ni < 2; ni++)
                wmma::load_matrix_sync(fb[ni], sW + (wn * 32 + ni * 16) * LDW + kk * 16, LDW);
            #pragma unroll
            for (int mi = 0; mi < 2; mi++) {
                wmma::fragment<wmma::matrix_a, 16, 16, 16, __nv_bfloat16, wmma::row_major> fa;
                wmma::load_matrix_sync(fa, sA + (wm * 32 + mi * 16) * LDW + kk * 16, LDW);
                #pragma unroll
                for (int ni = 0; ni < 2; ni++)
                    wmma::mma_sync(acc[mi][ni], fa, fb[ni], acc[mi][ni]);
            }
        }
        __syncthreads();   // done reading sA -> safe to overwrite with gates

        #pragma unroll
        for (int mi = 0; mi < 2; mi++)
            #pragma unroll
            for (int ni = 0; ni < 2; ni++)
                wmma::store_matrix_sync(sG + (wm * 32 + mi * 16) * LDG_ + (wn * 32 + ni * 16),
                                        acc[mi][ni], LDG_, wmma::mem_row_major);
        __syncthreads();

        // fused LSTM pointwise: 64 batch x 32 h, fast single-MUFU activations
        #pragma unroll
        for (int k = 0; k < 8; k++) {
            int i = threadIdx.x + k * 256;
            int bl = i >> 5, hl = i & 31;
            int b = b0 + bl;
            int ch = g_chars[t][b];
            const float* tab = g_tab[ch];
            int hcol = gt * 32 + hl;
            float gi = sG[bl * LDG_ + hl]      + tab[hcol];
            float gf = sG[bl * LDG_ + 32 + hl] + tab[H_ + hcol];
            float gg = sG[bl * LDG_ + 64 + hl] + tab[2 * H_ + hcol];
            float go = sG[bl * LDG_ + 96 + hl] + tab[3 * H_ + hcol];
            gi = sigmoid_fast(gi);
            gf = sigmoid_fast(gf);
            gg = tanh_fast(gg);
            go = sigmoid_fast(go);
            float c = fmaf(gf, creg[k], gi * gg);
            creg[k] = c;
            g_H[t + 1][b][hcol] = __float2bfloat16(go * tanh_fast(c));
        }

        // per-bt barrier across the 16 gt blocks
        __threadfence();
        __syncthreads();
        if (threadIdx.x == 0) {
            int v = atomicAdd(&g_cnt[bt * 32], 1);
            if (v == 15) {
                g_cnt[bt * 32] = 0;
                __threadfence();
                atomicExch((int*)&g_rel[bt * 32], t + 1);
            } else {
                while (g_rel[bt * 32] < t + 1) __nanosleep(32);
                __threadfence();
            }
        }
        __syncthreads();
    }
}

// ---------------- batched output projection ----------------
// grid (4 ntiles x 2048 mtiles), 256 threads = 8 warps (2m x 4n), tile 64m x 256n
__global__ __launch_bounds__(256, 2) void logits_kernel() {
    int nt = blockIdx.x, mt = blockIdx.y;
    __shared__ __nv_bfloat16 sA[64 * 72];
    __shared__ __nv_bfloat16 sB[256 * 72];
    const __nv_bfloat16* A = &g_H[1][0][0];  // [131072][512]

    int warp = threadIdx.x >> 5;
    int wm = warp >> 2;
    int wn = warp & 3;
    wmma::fragment<wmma::accumulator, 16, 16, 16, float> acc[2][4];
    #pragma unroll
    for (int mi = 0; mi < 2; mi++)
        #pragma unroll
        for (int ni = 0; ni < 4; ni++) wmma::fill_fragment(acc[mi][ni], 0.f);

    for (int kc = 0; kc < 8; kc++) {
        #pragma unroll
        for (int i = threadIdx.x; i < 512; i += 256) {
            int r = i >> 3, c8 = i & 7;
            *(uint4*)(sA + r * 72 + c8 * 8) = *(const uint4*)&A[(mt * 64 + r) * 512 + kc * 64 + c8 * 8];
        }
        #pragma unroll
        for (int i = threadIdx.x; i < 2048; i += 256) {
            int n = i >> 3, c8 = i & 7;
            *(uint4*)(sB + n * 72 + c8 * 8) = *(const uint4*)&g_Wout[nt * 256 + n][kc * 64 + c8 * 8];
        }
        __syncthreads();
        #pragma unroll
        for (int kk = 0; kk < 4; kk++) {
            wmma::fragment<wmma::matrix_a, 16, 16, 16, __nv_bfloat16, wmma::row_major> fa[2];
            #pragma unroll
            for (int mi = 0; mi < 2; mi++)
                wmma::load_matrix_sync(fa[mi], sA + (wm * 32 + mi * 16) * 72 + kk * 16, 72);
            #pragma unroll
            for (int ni = 0; ni < 4; ni++) {
                wmma::fragment<wmma::matrix_b, 16, 16, 16, __nv_bfloat16, wmma::col_major> fb;
                wmma::load_matrix_sync(fb, sB + (wn * 64 + ni * 16) * 72 + kk * 16, 72);
                #pragma unroll
                for (int mi = 0; mi < 2; mi++)
                    wmma::mma_sync(acc[mi][ni], fa[mi], fb, acc[mi][ni]);
            }
        }
        __syncthreads();
    }
    #pragma unroll
    for (int mi = 0; mi < 2; mi++)
        #pragma unroll
        for (int ni = 0; ni < 4; ni++) {
            int row = mt * 64 + wm * 32 + mi * 16;
            int col = nt * 256 + wn * 64 + ni * 16;
            wmma::store_matrix_sync(&g_logits[row][col], acc[mi][ni], 1024, wmma::mem_row_major);
        }
}

// ---------------- log_softmax + bias + remap (warp-shuffle reductions) ----------------
__global__ __launch_bounds__(256, 4) void softmax_kernel(float* __restrict__ out,
                                                         const float* __restrict__ bout) {
    int row = blockIdx.x;
    int t = row >> 9, b = row & 511;
    const float* lg = g_logits[row];
    __shared__ float red[8];

    int lane = threadIdx.x & 31;
    int warp = threadIdx.x >> 5;

    float v[4];
    float mx = -1e30f;
    #pragma unroll
    for (int j = 0; j < 4; j++) {
        int c = threadIdx.x + j * 256;
        v[j] = (c < V_) ? (lg[c] + bout[c]) : -1e30f;
        mx = fmaxf(mx, v[j]);
    }
    #pragma unroll
    for (int s = 16; s > 0; s >>= 1) mx = fmaxf(mx, __shfl_xor_sync(0xFFFFFFFF, mx, s));
    if (lane == 0) red[warp] = mx;
    __syncthreads();
    float m0 = red[lane & 7];
    #pragma unroll
    for (int s = 4; s > 0; s >>= 1) m0 = fmaxf(m0, __shfl_xor_sync(0xFFFFFFFF, m0, s));
    mx = m0;

    float sum = 0.f;
    #pragma unroll
    for (int j = 0; j < 4; j++) {
        int c = threadIdx.x + j * 256;
        if (c < V_) sum += __expf(v[j] - mx);
    }
    #pragma unroll
    for (int s = 16; s > 0; s >>= 1) sum += __shfl_xor_sync(0xFFFFFFFF, sum, s);
    __syncthreads();
    if (lane == 0) red[warp] = sum;
    __syncthreads();
    float s0 = red[lane & 7];
    #pragma unroll
    for (int s = 4; s > 0; s >>= 1) s0 += __shfl_xor_sync(0xFFFFFFFF, s0, s);
    float lse = mx + logf(s0);

    float* o = out + ((size_t)b * T_ + t) * V_;
    #pragma unroll
    for (int j = 0; j < 4; j++) {
        int c = threadIdx.x + j * 256;
        if (c < V_) o[c] = v[j] - lse;
    }
}

// ---------------- launch ----------------
extern "C" void kernel_launch(void* const* d_in, const int* in_sizes, int n_in,
                              void* d_out, int out_size) {
    const void*  gt   = d_in[1];
    const float* emb  = (const float*)d_in[2];
    const float* Wih1 = (const float*)d_in[7];
    const float* Whh1 = (const float*)d_in[8];
    const float* bih1 = (const float*)d_in[9];
    const float* bhh1 = (const float*)d_in[10];
    const float* Wout = (const float*)d_in[11];
    const float* bout = (const float*)d_in[12];
    float* out = (float*)d_out;

    cudaFuncSetAttribute(recur_kernel, cudaFuncAttributeMaxDynamicSharedMemorySize, SMEM_BYTES);

    init_kernel<<<1024, 256>>>(Whh1, Wout, gt);
    table_kernel<<<dim3(32, 16), 256>>>(emb, Wih1, bih1, bhh1);
    recur_kernel<<<128, 256, SMEM_BYTES>>>();
    logits_kernel<<<dim3(4, 2048), 256>>>();
    softmax_kernel<<<T_ * B_, 256>>>(out, bout);
}